// round 7
// baseline (speedup 1.0000x reference)
#include <cuda_runtime.h>
#include <cstdint>

#define B_  64
#define T_  2048
#define I_  128
#define H_  256
#define C_  64
#define G3  (3 * H_)   // 768

__device__ float g_gates[(size_t)B_ * T_ * G3];
__device__ float g_h[(size_t)B_ * T_ * H_];

// ---------------------------------------------------------------------------
// helpers
// ---------------------------------------------------------------------------
__device__ __forceinline__ float sigmoidf_(float x) {
    return 1.0f / (1.0f + __expf(-x));
}
__device__ __forceinline__ float tanhf_(float x) {
    return 2.0f / (1.0f + __expf(-2.0f * x)) - 1.0f;
}
__device__ __forceinline__ void fma2_(uint64_t& d, uint64_t a, uint64_t b) {
    asm("fma.rn.f32x2 %0, %1, %2, %0;" : "+l"(d) : "l"(a), "l"(b));
}
__device__ __forceinline__ float f2lo_(uint64_t v) {
    float lo, hi;
    asm("mov.b64 {%0,%1}, %2;" : "=f"(lo), "=f"(hi) : "l"(v));
    return lo;
}
__device__ __forceinline__ float f2hi_(uint64_t v) {
    float lo, hi;
    asm("mov.b64 {%0,%1}, %2;" : "=f"(lo), "=f"(hi) : "l"(v));
    return hi;
}
__device__ __forceinline__ uint64_t dup2_(float x) {
    uint64_t r;
    asm("mov.b64 %0, {%1,%1};" : "=l"(r) : "f"(x));
    return r;
}
__device__ __forceinline__ uint64_t pack2_(float lo, float hi) {
    uint64_t r;
    asm("mov.b64 %0, {%1,%2};" : "=l"(r) : "f"(lo), "f"(hi));
    return r;
}
__device__ __forceinline__ void mbar_init_(uint32_t a, uint32_t cnt) {
    asm volatile("mbarrier.init.shared.b64 [%0], %1;" :: "r"(a), "r"(cnt) : "memory");
}
__device__ __forceinline__ void mbar_arm_(uint32_t a, uint32_t tx) {
    asm volatile("mbarrier.arrive.expect_tx.shared.b64 _, [%0], %1;"
                 :: "r"(a), "r"(tx) : "memory");
}
__device__ __forceinline__ void mbar_wait_(uint32_t a, uint32_t par) {
    uint32_t done;
    asm volatile(
        "{\n\t.reg .pred p;\n\t"
        "mbarrier.try_wait.parity.acquire.cta.shared::cta.b64 p, [%1], %2;\n\t"
        "selp.b32 %0, 1, 0, p;\n\t}"
        : "=r"(done) : "r"(a), "r"(par) : "memory");
    if (!done) {
        asm volatile(
            "{\n\t.reg .pred P1;\n\t"
            "W_%=:\n\t"
            "mbarrier.try_wait.parity.acquire.cta.shared::cta.b64 P1, [%0], %1, 0x989680;\n\t"
            "@P1 bra.uni D_%=;\n\t"
            "bra.uni W_%=;\n\t"
            "D_%=:\n\t}"
            :: "r"(a), "r"(par) : "memory");
    }
}

// ---------------------------------------------------------------------------
// GEMM (double-buffered, f32x2 inner) — unchanged from R5/R6.
// ---------------------------------------------------------------------------
__global__ void __launch_bounds__(256) gemm_nt(
    const float* __restrict__ A, const float* __restrict__ Bm,
    const float* __restrict__ bias, float* __restrict__ C,
    int M, int N, int K)
{
    const int BM = 128, BN = 64, BK = 16;
    __shared__ float As[2][BK * BM];
    __shared__ float Bs[2][BK * BN];

    int tid = threadIdx.x;
    int tx = tid & 15;
    int ty = tid >> 4;
    int m0 = blockIdx.y * BM;
    int n0 = blockIdx.x * BN;

    const int a_row0 = tid >> 2, a_c4 = tid & 3;
    const int b_row  = tid >> 2, b_c4 = tid & 3;

    uint64_t acc2[4][4];
#pragma unroll
    for (int i = 0; i < 4; i++)
#pragma unroll
        for (int j = 0; j < 4; j++) acc2[i][j] = 0ull;

    float4 a_stg0, a_stg1, b_stg;

    a_stg0 = *(const float4*)&A[(size_t)(m0 + a_row0) * K + a_c4 * 4];
    a_stg1 = *(const float4*)&A[(size_t)(m0 + a_row0 + 64) * K + a_c4 * 4];
    b_stg  = *(const float4*)&Bm[(size_t)(n0 + b_row) * K + b_c4 * 4];
    {
        float* as = As[0]; float* bs = Bs[0];
        as[(a_c4 * 4 + 0) * BM + a_row0] = a_stg0.x;
        as[(a_c4 * 4 + 1) * BM + a_row0] = a_stg0.y;
        as[(a_c4 * 4 + 2) * BM + a_row0] = a_stg0.z;
        as[(a_c4 * 4 + 3) * BM + a_row0] = a_stg0.w;
        as[(a_c4 * 4 + 0) * BM + a_row0 + 64] = a_stg1.x;
        as[(a_c4 * 4 + 1) * BM + a_row0 + 64] = a_stg1.y;
        as[(a_c4 * 4 + 2) * BM + a_row0 + 64] = a_stg1.z;
        as[(a_c4 * 4 + 3) * BM + a_row0 + 64] = a_stg1.w;
        bs[(b_c4 * 4 + 0) * BN + b_row] = b_stg.x;
        bs[(b_c4 * 4 + 1) * BN + b_row] = b_stg.y;
        bs[(b_c4 * 4 + 2) * BN + b_row] = b_stg.z;
        bs[(b_c4 * 4 + 3) * BN + b_row] = b_stg.w;
    }
    __syncthreads();

    int p = 0;
    for (int kt = 0; kt < K; kt += BK) {
        const bool has_next = (kt + BK) < K;
        if (has_next) {
            a_stg0 = *(const float4*)&A[(size_t)(m0 + a_row0) * K + kt + BK + a_c4 * 4];
            a_stg1 = *(const float4*)&A[(size_t)(m0 + a_row0 + 64) * K + kt + BK + a_c4 * 4];
            b_stg  = *(const float4*)&Bm[(size_t)(n0 + b_row) * K + kt + BK + b_c4 * 4];
        }

        const float* as = As[p];
        const float* bs = Bs[p];
#pragma unroll
        for (int k = 0; k < BK; k++) {
            const uint64_t* a2 = (const uint64_t*)&as[k * BM + ty * 8];
            uint64_t av0 = a2[0], av1 = a2[1], av2 = a2[2], av3 = a2[3];
            float4 bq = *(const float4*)&bs[k * BN + tx * 4];
            uint64_t b0 = dup2_(bq.x), b1 = dup2_(bq.y);
            uint64_t b2 = dup2_(bq.z), b3 = dup2_(bq.w);
            fma2_(acc2[0][0], av0, b0); fma2_(acc2[0][1], av0, b1);
            fma2_(acc2[0][2], av0, b2); fma2_(acc2[0][3], av0, b3);
            fma2_(acc2[1][0], av1, b0); fma2_(acc2[1][1], av1, b1);
            fma2_(acc2[1][2], av1, b2); fma2_(acc2[1][3], av1, b3);
            fma2_(acc2[2][0], av2, b0); fma2_(acc2[2][1], av2, b1);
            fma2_(acc2[2][2], av2, b2); fma2_(acc2[2][3], av2, b3);
            fma2_(acc2[3][0], av3, b0); fma2_(acc2[3][1], av3, b1);
            fma2_(acc2[3][2], av3, b2); fma2_(acc2[3][3], av3, b3);
        }

        if (has_next) {
            float* asn = As[p ^ 1]; float* bsn = Bs[p ^ 1];
            asn[(a_c4 * 4 + 0) * BM + a_row0] = a_stg0.x;
            asn[(a_c4 * 4 + 1) * BM + a_row0] = a_stg0.y;
            asn[(a_c4 * 4 + 2) * BM + a_row0] = a_stg0.z;
            asn[(a_c4 * 4 + 3) * BM + a_row0] = a_stg0.w;
            asn[(a_c4 * 4 + 0) * BM + a_row0 + 64] = a_stg1.x;
            asn[(a_c4 * 4 + 1) * BM + a_row0 + 64] = a_stg1.y;
            asn[(a_c4 * 4 + 2) * BM + a_row0 + 64] = a_stg1.z;
            asn[(a_c4 * 4 + 3) * BM + a_row0 + 64] = a_stg1.w;
            bsn[(b_c4 * 4 + 0) * BN + b_row] = b_stg.x;
            bsn[(b_c4 * 4 + 1) * BN + b_row] = b_stg.y;
            bsn[(b_c4 * 4 + 2) * BN + b_row] = b_stg.z;
            bsn[(b_c4 * 4 + 3) * BN + b_row] = b_stg.w;
            __syncthreads();
        }
        p ^= 1;
    }

    float4 bv = *(const float4*)&bias[n0 + tx * 4];
#pragma unroll
    for (int ii = 0; ii < 4; ii++) {
        float4 oe, oo;
        oe.x = f2lo_(acc2[ii][0]) + bv.x;
        oe.y = f2lo_(acc2[ii][1]) + bv.y;
        oe.z = f2lo_(acc2[ii][2]) + bv.z;
        oe.w = f2lo_(acc2[ii][3]) + bv.w;
        oo.x = f2hi_(acc2[ii][0]) + bv.x;
        oo.y = f2hi_(acc2[ii][1]) + bv.y;
        oo.z = f2hi_(acc2[ii][2]) + bv.z;
        oo.w = f2hi_(acc2[ii][3]) + bv.w;
        *(float4*)&C[(size_t)(m0 + ty * 8 + 2 * ii) * N + n0 + tx * 4] = oe;
        *(float4*)&C[(size_t)(m0 + ty * 8 + 2 * ii + 1) * N + n0 + tx * 4] = oo;
    }
}

// ---------------------------------------------------------------------------
// GRU recurrent scan, v6: R4 fused matvec + (a) single mbarrier per step,
// (b) column-pair epilogue on warps 0-1 with b64 packed st.async (256
// transactions/step instead of 1024), (c) named-barrier gh hand-off so
// warps 2-11 free-run to the next wait.
//
// hq layout (R4): [p][half][kk][4], quad = {b0_2k, b0_2k+1, b1_2k, b1_2k+1};
// half stride 260 floats (+16B bank shift between ks halves).
// ---------------------------------------------------------------------------
#define HQ_HALF 260
#define HQ_P    (2 * HQ_HALF)   // 520 floats per phase buffer
#define TXB     2048u           // 512 h floats * 4B per CTA per step

__global__ void __cluster_dims__(4, 1, 1) __launch_bounds__(384, 1)
gru_scan(const float* __restrict__ gates, const float* __restrict__ Whh,
         const float* __restrict__ bhh, float* __restrict__ hout)
{
    __shared__ float hq[2 * HQ_P];
    __shared__ float gh_s[2 * 192];    // [b][row]
    __shared__ float bh_s[192];
    __shared__ __align__(8) uint64_t mbar_s[2];

    int tid = threadIdx.x;
    int wid = tid >> 5;
    uint32_t rank;
    asm("mov.u32 %0, %%cluster_ctarank;" : "=r"(rank));
    int b0 = (blockIdx.x >> 2) * 2;

    const int row = tid >> 1;          // 0..191 = g*64 + jl
    const int ks  = tid & 1;
    const int g   = row >> 6;
    const int jl  = row & 63;
    const int grow = g * H_ + (int)rank * 64 + jl;

    // W_hh row-half -> 64 packed b64 registers (once).
    uint64_t wr[64];
    const uint64_t* wsrc = (const uint64_t*)&Whh[(size_t)grow * H_ + ks * 128];
#pragma unroll
    for (int kk = 0; kk < 64; kk++) wr[kk] = wsrc[kk];

    uint32_t hq_u32   = (uint32_t)__cvta_generic_to_shared(hq);
    uint32_t mbar_u32 = (uint32_t)__cvta_generic_to_shared(mbar_s);

    if (tid < 192) {
        int gg = tid >> 6, jj = tid & 63;
        bh_s[tid] = bhh[gg * H_ + (int)rank * 64 + jj];
    }
    for (int i = tid; i < 2 * HQ_P; i += 384) hq[i] = 0.0f;
    if (tid == 0) {
        mbar_init_(mbar_u32, 1);
        mbar_init_(mbar_u32 + 8, 1);
        mbar_arm_(mbar_u32 + 8, TXB);   // arm mbar[1] for step-0 writes
    }
    __syncthreads();
    asm volatile("barrier.cluster.arrive.aligned;" ::: "memory");
    asm volatile("barrier.cluster.wait.aligned;" ::: "memory");

    const uint32_t ks_off = (uint32_t)ks * (HQ_HALF * 4);

    // Epilogue mapping: threads 0..63 (warps 0-1). Thread e handles batch
    // bb = e>>5 and local column pair (2*kp, 2*kp+1), kp = e&31.
    const int ebb = (tid >> 5) & 1;
    const int ekp = tid & 31;
    const int jg0 = (int)rank * 64 + 2 * ekp;          // even global column
    // quad slot base for (jg0, jg0+1) of batch ebb inside a phase buffer:
    const int qbase = (jg0 >> 7) * HQ_HALF + ((jg0 & 127) >> 1) * 4 + ebb * 2;

    uint32_t ph = 0;   // parity bits for mbar[0], mbar[1]
    for (int t = 0; t < T_; t++) {
        const int buf = t & 1;
        const int nxt = buf ^ 1;

        // Prefetch gates_x (epilogue threads only; float2 per gate).
        float2 xr2, xz2, xn2;
        if (tid < 64) {
            const float* gp = &gates[((size_t)(b0 + ebb) * T_ + t) * G3 + jg0];
            xr2 = __ldg((const float2*)(gp));
            xz2 = __ldg((const float2*)(gp + 256));
            xn2 = __ldg((const float2*)(gp + 512));
        }

        if (t) {
            mbar_wait_(mbar_u32 + buf * 8, (ph >> buf) & 1u);
            ph ^= (1u << buf);
        }
        // Re-arm for use at step t+2 (writers for t+2 are gated by mbar[nxt],
        // which needs our step-t sends, issued after this point).
        if (tid == 0) mbar_arm_(mbar_u32 + buf * 8, TXB);

        // Fused matvec, both batches (identical arithmetic to R4).
        uint32_t hb = hq_u32 + (uint32_t)buf * (HQ_P * 4) + ks_off;
        uint64_t a00 = 0, a01 = 0, a10 = 0, a11 = 0;
#pragma unroll
        for (int kk = 0; kk < 64; kk += 2) {
            uint64_t hx0, hy0, hx1, hy1;
            asm volatile("ld.shared.v2.u64 {%0,%1}, [%2];"
                         : "=l"(hx0), "=l"(hy0) : "r"(hb + kk * 16));
            asm volatile("ld.shared.v2.u64 {%0,%1}, [%2];"
                         : "=l"(hx1), "=l"(hy1) : "r"(hb + kk * 16 + 16));
            fma2_(a00, wr[kk], hx0);
            fma2_(a10, wr[kk], hy0);
            fma2_(a01, wr[kk + 1], hx1);
            fma2_(a11, wr[kk + 1], hy1);
        }
        float s0 = (f2lo_(a00) + f2hi_(a00)) + (f2lo_(a01) + f2hi_(a01));
        float s1 = (f2lo_(a10) + f2hi_(a10)) + (f2lo_(a11) + f2hi_(a11));
        s0 += __shfl_xor_sync(0xffffffffu, s0, 1);
        s1 += __shfl_xor_sync(0xffffffffu, s1, 1);
        if (ks == 0) {
            float bh = bh_s[row];
            gh_s[row]       = s0 + bh;
            gh_s[192 + row] = s1 + bh;
        }

        if (wid < 2) {
            asm volatile("bar.sync 1, 384;" ::: "memory");   // gh ready
            // Epilogue: 2 columns (jg0, jg0+1) of batch ebb.
            const float* ghp = &gh_s[ebb * 192 + 2 * ekp];
            float r0 = sigmoidf_(xr2.x + ghp[0]);
            float r1 = sigmoidf_(xr2.y + ghp[1]);
            float z0 = sigmoidf_(xz2.x + ghp[64]);
            float z1 = sigmoidf_(xz2.y + ghp[65]);
            float n0 = tanhf_(xn2.x + r0 * ghp[128]);
            float n1 = tanhf_(xn2.y + r1 * ghp[129]);
            float h0 = hq[buf * HQ_P + qbase];
            float h1 = hq[buf * HQ_P + qbase + 1];
            float hn0 = (1.0f - z0) * n0 + z0 * h0;
            float hn1 = (1.0f - z1) * n1 + z1 * h1;

            uint64_t hv = pack2_(hn0, hn1);
            uint32_t dst = hq_u32 + (uint32_t)(nxt * HQ_P + qbase) * 4;
            uint32_t mb  = mbar_u32 + nxt * 8;
#pragma unroll
            for (uint32_t tc = 0; tc < 4; tc++) {
                asm volatile(
                    "{\n\t.reg .b32 ra, rb;\n\t"
                    "mapa.shared::cluster.u32 ra, %0, %2;\n\t"
                    "mapa.shared::cluster.u32 rb, %1, %2;\n\t"
                    "st.async.shared::cluster.mbarrier::complete_tx::bytes.b64 "
                    "[ra], %3, [rb];\n\t}"
                    :: "r"(dst), "r"(mb), "r"(tc), "l"(hv) : "memory");
            }
            *(float2*)&hout[((size_t)(b0 + ebb) * T_ + t) * H_ + jg0] =
                make_float2(hn0, hn1);
        } else {
            asm volatile("bar.arrive 1, 384;" ::: "memory");
        }
    }

    // Drain inbound st.async before exit.
    mbar_wait_(mbar_u32, ph & 1u);
    asm volatile("barrier.cluster.arrive.aligned;" ::: "memory");
    asm volatile("barrier.cluster.wait.aligned;" ::: "memory");
}

// ---------------------------------------------------------------------------
extern "C" void kernel_launch(void* const* d_in, const int* in_sizes, int n_in,
                              void* d_out, int out_size)
{
    const float* x    = (const float*)d_in[0];
    const float* Wih0 = (const float*)d_in[1];
    const float* Whh0 = (const float*)d_in[2];
    const float* bih0 = (const float*)d_in[3];
    const float* bhh0 = (const float*)d_in[4];
    const float* Wih1 = (const float*)d_in[5];
    const float* Whh1 = (const float*)d_in[6];
    const float* bih1 = (const float*)d_in[7];
    const float* bhh1 = (const float*)d_in[8];
    const float* fcw  = (const float*)d_in[9];
    const float* fcb  = (const float*)d_in[10];
    float* out = (float*)d_out;

    float *gates, *h;
    cudaGetSymbolAddress((void**)&gates, g_gates);
    cudaGetSymbolAddress((void**)&h, g_h);

    const int M = B_ * T_;
    dim3 blk(256);

    gemm_nt<<<dim3(G3 / 64, M / 128), blk>>>(x, Wih0, bih0, gates, M, G3, I_);
    gru_scan<<<128, 384>>>(gates, Whh0, bhh0, h);

    gemm_nt<<<dim3(G3 / 64, M / 128), blk>>>(h, Wih1, bih1, gates, M, G3, H_);
    gru_scan<<<128, 384>>>(gates, Whh1, bhh1, h);

    gemm_nt<<<dim3(C_ / 64, M / 128), blk>>>(h, fcw, fcb, out, M, C_, H_);
}

// round 8
// speedup vs baseline: 1.3506x; 1.3506x over previous
#include <cuda_runtime.h>
#include <cstdint>

#define B_  64
#define T_  2048
#define I_  128
#define H_  256
#define C_  64
#define G3  (3 * H_)   // 768

__device__ float g_gates[(size_t)B_ * T_ * G3];
__device__ float g_h[(size_t)B_ * T_ * H_];

// ---------------------------------------------------------------------------
// helpers
// ---------------------------------------------------------------------------
__device__ __forceinline__ float sigmoidf_(float x) {
    return 1.0f / (1.0f + __expf(-x));
}
__device__ __forceinline__ float tanhf_(float x) {
    return 2.0f / (1.0f + __expf(-2.0f * x)) - 1.0f;
}
__device__ __forceinline__ void fma2_(uint64_t& d, uint64_t a, uint64_t b) {
    asm("fma.rn.f32x2 %0, %1, %2, %0;" : "+l"(d) : "l"(a), "l"(b));
}
__device__ __forceinline__ float f2lo_(uint64_t v) {
    float lo, hi;
    asm("mov.b64 {%0,%1}, %2;" : "=f"(lo), "=f"(hi) : "l"(v));
    return lo;
}
__device__ __forceinline__ float f2hi_(uint64_t v) {
    float lo, hi;
    asm("mov.b64 {%0,%1}, %2;" : "=f"(lo), "=f"(hi) : "l"(v));
    return hi;
}
__device__ __forceinline__ uint64_t dup2_(float x) {
    uint64_t r;
    asm("mov.b64 %0, {%1,%1};" : "=l"(r) : "f"(x));
    return r;
}
__device__ __forceinline__ void mbar_init_(uint32_t a, uint32_t cnt) {
    asm volatile("mbarrier.init.shared.b64 [%0], %1;" :: "r"(a), "r"(cnt) : "memory");
}
__device__ __forceinline__ void mbar_arm_(uint32_t a, uint32_t tx) {
    asm volatile("mbarrier.arrive.expect_tx.shared.b64 _, [%0], %1;"
                 :: "r"(a), "r"(tx) : "memory");
}
__device__ __forceinline__ void mbar_wait_(uint32_t a, uint32_t par) {
    uint32_t done;
    asm volatile(
        "{\n\t.reg .pred p;\n\t"
        "mbarrier.try_wait.parity.acquire.cta.shared::cta.b64 p, [%1], %2;\n\t"
        "selp.b32 %0, 1, 0, p;\n\t}"
        : "=r"(done) : "r"(a), "r"(par) : "memory");
    if (!done) {
        asm volatile(
            "{\n\t.reg .pred P1;\n\t"
            "W_%=:\n\t"
            "mbarrier.try_wait.parity.acquire.cta.shared::cta.b64 P1, [%0], %1, 0x989680;\n\t"
            "@P1 bra.uni D_%=;\n\t"
            "bra.uni W_%=;\n\t"
            "D_%=:\n\t}"
            :: "r"(a), "r"(par) : "memory");
    }
}

// ---------------------------------------------------------------------------
// GEMM (double-buffered, f32x2 inner) — unchanged from R5.
// ---------------------------------------------------------------------------
__global__ void __launch_bounds__(256) gemm_nt(
    const float* __restrict__ A, const float* __restrict__ Bm,
    const float* __restrict__ bias, float* __restrict__ C,
    int M, int N, int K)
{
    const int BM = 128, BN = 64, BK = 16;
    __shared__ float As[2][BK * BM];
    __shared__ float Bs[2][BK * BN];

    int tid = threadIdx.x;
    int tx = tid & 15;
    int ty = tid >> 4;
    int m0 = blockIdx.y * BM;
    int n0 = blockIdx.x * BN;

    const int a_row0 = tid >> 2, a_c4 = tid & 3;
    const int b_row  = tid >> 2, b_c4 = tid & 3;

    uint64_t acc2[4][4];
#pragma unroll
    for (int i = 0; i < 4; i++)
#pragma unroll
        for (int j = 0; j < 4; j++) acc2[i][j] = 0ull;

    float4 a_stg0, a_stg1, b_stg;

    a_stg0 = *(const float4*)&A[(size_t)(m0 + a_row0) * K + a_c4 * 4];
    a_stg1 = *(const float4*)&A[(size_t)(m0 + a_row0 + 64) * K + a_c4 * 4];
    b_stg  = *(const float4*)&Bm[(size_t)(n0 + b_row) * K + b_c4 * 4];
    {
        float* as = As[0]; float* bs = Bs[0];
        as[(a_c4 * 4 + 0) * BM + a_row0] = a_stg0.x;
        as[(a_c4 * 4 + 1) * BM + a_row0] = a_stg0.y;
        as[(a_c4 * 4 + 2) * BM + a_row0] = a_stg0.z;
        as[(a_c4 * 4 + 3) * BM + a_row0] = a_stg0.w;
        as[(a_c4 * 4 + 0) * BM + a_row0 + 64] = a_stg1.x;
        as[(a_c4 * 4 + 1) * BM + a_row0 + 64] = a_stg1.y;
        as[(a_c4 * 4 + 2) * BM + a_row0 + 64] = a_stg1.z;
        as[(a_c4 * 4 + 3) * BM + a_row0 + 64] = a_stg1.w;
        bs[(b_c4 * 4 + 0) * BN + b_row] = b_stg.x;
        bs[(b_c4 * 4 + 1) * BN + b_row] = b_stg.y;
        bs[(b_c4 * 4 + 2) * BN + b_row] = b_stg.z;
        bs[(b_c4 * 4 + 3) * BN + b_row] = b_stg.w;
    }
    __syncthreads();

    int p = 0;
    for (int kt = 0; kt < K; kt += BK) {
        const bool has_next = (kt + BK) < K;
        if (has_next) {
            a_stg0 = *(const float4*)&A[(size_t)(m0 + a_row0) * K + kt + BK + a_c4 * 4];
            a_stg1 = *(const float4*)&A[(size_t)(m0 + a_row0 + 64) * K + kt + BK + a_c4 * 4];
            b_stg  = *(const float4*)&Bm[(size_t)(n0 + b_row) * K + kt + BK + b_c4 * 4];
        }

        const float* as = As[p];
        const float* bs = Bs[p];
#pragma unroll
        for (int k = 0; k < BK; k++) {
            const uint64_t* a2 = (const uint64_t*)&as[k * BM + ty * 8];
            uint64_t av0 = a2[0], av1 = a2[1], av2 = a2[2], av3 = a2[3];
            float4 bq = *(const float4*)&bs[k * BN + tx * 4];
            uint64_t b0 = dup2_(bq.x), b1 = dup2_(bq.y);
            uint64_t b2 = dup2_(bq.z), b3 = dup2_(bq.w);
            fma2_(acc2[0][0], av0, b0); fma2_(acc2[0][1], av0, b1);
            fma2_(acc2[0][2], av0, b2); fma2_(acc2[0][3], av0, b3);
            fma2_(acc2[1][0], av1, b0); fma2_(acc2[1][1], av1, b1);
            fma2_(acc2[1][2], av1, b2); fma2_(acc2[1][3], av1, b3);
            fma2_(acc2[2][0], av2, b0); fma2_(acc2[2][1], av2, b1);
            fma2_(acc2[2][2], av2, b2); fma2_(acc2[2][3], av2, b3);
            fma2_(acc2[3][0], av3, b0); fma2_(acc2[3][1], av3, b1);
            fma2_(acc2[3][2], av3, b2); fma2_(acc2[3][3], av3, b3);
        }

        if (has_next) {
            float* asn = As[p ^ 1]; float* bsn = Bs[p ^ 1];
            asn[(a_c4 * 4 + 0) * BM + a_row0] = a_stg0.x;
            asn[(a_c4 * 4 + 1) * BM + a_row0] = a_stg0.y;
            asn[(a_c4 * 4 + 2) * BM + a_row0] = a_stg0.z;
            asn[(a_c4 * 4 + 3) * BM + a_row0] = a_stg0.w;
            asn[(a_c4 * 4 + 0) * BM + a_row0 + 64] = a_stg1.x;
            asn[(a_c4 * 4 + 1) * BM + a_row0 + 64] = a_stg1.y;
            asn[(a_c4 * 4 + 2) * BM + a_row0 + 64] = a_stg1.z;
            asn[(a_c4 * 4 + 3) * BM + a_row0 + 64] = a_stg1.w;
            bsn[(b_c4 * 4 + 0) * BN + b_row] = b_stg.x;
            bsn[(b_c4 * 4 + 1) * BN + b_row] = b_stg.y;
            bsn[(b_c4 * 4 + 2) * BN + b_row] = b_stg.z;
            bsn[(b_c4 * 4 + 3) * BN + b_row] = b_stg.w;
            __syncthreads();
        }
        p ^= 1;
    }

    float4 bv = *(const float4*)&bias[n0 + tx * 4];
#pragma unroll
    for (int ii = 0; ii < 4; ii++) {
        float4 oe, oo;
        oe.x = f2lo_(acc2[ii][0]) + bv.x;
        oe.y = f2lo_(acc2[ii][1]) + bv.y;
        oe.z = f2lo_(acc2[ii][2]) + bv.z;
        oe.w = f2lo_(acc2[ii][3]) + bv.w;
        oo.x = f2hi_(acc2[ii][0]) + bv.x;
        oo.y = f2hi_(acc2[ii][1]) + bv.y;
        oo.z = f2hi_(acc2[ii][2]) + bv.z;
        oo.w = f2hi_(acc2[ii][3]) + bv.w;
        *(float4*)&C[(size_t)(m0 + ty * 8 + 2 * ii) * N + n0 + tx * 4] = oe;
        *(float4*)&C[(size_t)(m0 + ty * 8 + 2 * ii + 1) * N + n0 + tx * 4] = oo;
    }
}

// ---------------------------------------------------------------------------
// GRU recurrent scan, v7 = R4 structure + bulk DSMEM exchange.
// Epilogue (128 thr) stages h_new into a local 512B block; one elected
// thread sends it to all 4 CTAs with cp.async.bulk (complete_tx on the
// target's mbarrier): 4 transactions/step instead of 512.
//
// hq layout (R4): [p][half][kkpair][4], quad={b0_2k,b0_2k+1,b1_2k,b1_2k+1};
// half stride 260 floats. Rank r's slice (global pairs r*32..r*32+31) is a
// contiguous 512B block at byte offset (r>>1)*1040 + (r&1)*512.
// ---------------------------------------------------------------------------
#define HQ_HALF 260
#define HQ_P    (2 * HQ_HALF)   // 520 floats per phase buffer
#define TXB     2048u           // 4 sources * 512B per CTA per step

__global__ void __cluster_dims__(4, 1, 1) __launch_bounds__(384, 1)
gru_scan(const float* __restrict__ gates, const float* __restrict__ Whh,
         const float* __restrict__ bhh, float* __restrict__ hout)
{
    __shared__ __align__(16) float hq[2 * HQ_P];
    __shared__ __align__(16) float stag[2][128];   // staging, per phase
    __shared__ float gh_s[2 * 192];                // [b][row]
    __shared__ float bh_s[192];
    __shared__ __align__(8) uint64_t mbar_s[2];

    int tid = threadIdx.x;
    uint32_t rank;
    asm("mov.u32 %0, %%cluster_ctarank;" : "=r"(rank));
    int b0 = (blockIdx.x >> 2) * 2;

    const int row = tid >> 1;          // 0..191 = g*64 + jl
    const int ks  = tid & 1;
    const int g   = row >> 6;
    const int jl  = row & 63;
    const int grow = g * H_ + (int)rank * 64 + jl;

    // W_hh row-half -> 64 packed b64 registers (once).
    uint64_t wr[64];
    const uint64_t* wsrc = (const uint64_t*)&Whh[(size_t)grow * H_ + ks * 128];
#pragma unroll
    for (int kk = 0; kk < 64; kk++) wr[kk] = wsrc[kk];

    uint32_t hq_u32   = (uint32_t)__cvta_generic_to_shared(hq);
    uint32_t stag_u32 = (uint32_t)__cvta_generic_to_shared(stag);
    uint32_t mbar_u32 = (uint32_t)__cvta_generic_to_shared(mbar_s);

    if (tid < 192) {
        int gg = tid >> 6, jj = tid & 63;
        bh_s[tid] = bhh[gg * H_ + (int)rank * 64 + jj];
    }
    for (int i = tid; i < 2 * HQ_P; i += 384) hq[i] = 0.0f;
    if (tid == 0) {
        mbar_init_(mbar_u32, 1);
        mbar_init_(mbar_u32 + 8, 1);
        mbar_arm_(mbar_u32 + 8, TXB);   // arm mbar[1] for step-0 sends
    }
    __syncthreads();
    asm volatile("barrier.cluster.arrive.aligned;" ::: "memory");
    asm volatile("barrier.cluster.wait.aligned;" ::: "memory");

    const uint32_t ks_off = (uint32_t)ks * (HQ_HALF * 4);

    // Epilogue mapping (threads 0..127): batch bb, local column jl_e.
    const int jl_e = tid & 63;
    const int bb   = (tid >> 6) & 1;
    const int jg   = (int)rank * 64 + jl_e;
    const int hidx = ((jg >> 7) * HQ_HALF) + (((jg & 127) >> 1) << 2)
                   + bb * 2 + (jg & 1);
    // staging slot: quad per local pair {b0_2k, b0_2k+1, b1_2k, b1_2k+1}
    const int sidx = ((jl_e >> 1) << 2) + bb * 2 + (jl_e & 1);
    // destination byte offset of this rank's slice inside a phase buffer
    const uint32_t dst_off = (rank >> 1) * (HQ_HALF * 4) + (rank & 1) * 512;

    uint32_t ph = 0;   // parity bits for mbar[0], mbar[1]
    for (int t = 0; t < T_; t++) {
        const int buf = t & 1;
        const int nxt = buf ^ 1;

        // Prefetch gates_x (independent of h).
        float xr = 0.f, xz = 0.f, xn = 0.f;
        if (tid < 128) {
            const float* gp = &gates[((size_t)(b0 + bb) * T_ + t) * G3];
            xr = __ldg(gp + jg);
            xz = __ldg(gp + 256 + jg);
            xn = __ldg(gp + 512 + jg);
        }

        if (t) {
            mbar_wait_(mbar_u32 + buf * 8, (ph >> buf) & 1u);
            ph ^= (1u << buf);
        }
        // Re-arm this buffer's barrier for step t+2 (ordering proof as R4;
        // arm and sends are both on tid 0, so program order suffices).
        if (tid == 0) mbar_arm_(mbar_u32 + buf * 8, TXB);

        // Fused matvec, both batches (bit-identical to R4).
        uint32_t hb = hq_u32 + (uint32_t)buf * (HQ_P * 4) + ks_off;
        uint64_t a00 = 0, a01 = 0, a10 = 0, a11 = 0;
#pragma unroll
        for (int kk = 0; kk < 64; kk += 2) {
            uint64_t hx0, hy0, hx1, hy1;
            asm volatile("ld.shared.v2.u64 {%0,%1}, [%2];"
                         : "=l"(hx0), "=l"(hy0) : "r"(hb + kk * 16));
            asm volatile("ld.shared.v2.u64 {%0,%1}, [%2];"
                         : "=l"(hx1), "=l"(hy1) : "r"(hb + kk * 16 + 16));
            fma2_(a00, wr[kk], hx0);
            fma2_(a10, wr[kk], hy0);
            fma2_(a01, wr[kk + 1], hx1);
            fma2_(a11, wr[kk + 1], hy1);
        }
        float s0 = (f2lo_(a00) + f2hi_(a00)) + (f2lo_(a01) + f2hi_(a01));
        float s1 = (f2lo_(a10) + f2hi_(a10)) + (f2lo_(a11) + f2hi_(a11));
        s0 += __shfl_xor_sync(0xffffffffu, s0, 1);
        s1 += __shfl_xor_sync(0xffffffffu, s1, 1);
        if (ks == 0) {
            float bh = bh_s[row];
            gh_s[row]       = s0 + bh;
            gh_s[192 + row] = s1 + bh;
        }
        __syncthreads();

        if (tid < 128) {
            float r = sigmoidf_(xr + gh_s[bb * 192 + jl_e]);
            float z = sigmoidf_(xz + gh_s[bb * 192 + 64 + jl_e]);
            float n = tanhf_(xn + r * gh_s[bb * 192 + 128 + jl_e]);
            float hold = hq[buf * HQ_P + hidx];
            float hnew = (1.0f - z) * n + z * hold;

            stag[nxt][sidx] = hnew;
            hout[((size_t)(b0 + bb) * T_ + t) * H_ + jg] = hnew;

            // All staging writes visible, then one thread bulk-sends the
            // 512B slice to every CTA in the cluster.
            asm volatile("bar.sync 1, 128;" ::: "memory");
            if (tid == 0) {
                asm volatile("fence.proxy.async.shared::cta;" ::: "memory");
                uint32_t src = stag_u32 + (uint32_t)nxt * 512;
                uint32_t dst = hq_u32 + (uint32_t)nxt * (HQ_P * 4) + dst_off;
                uint32_t mb  = mbar_u32 + nxt * 8;
#pragma unroll
                for (uint32_t tc = 0; tc < 4; tc++) {
                    asm volatile(
                        "{\n\t.reg .b32 ra, rb;\n\t"
                        "mapa.shared::cluster.u32 ra, %0, %3;\n\t"
                        "mapa.shared::cluster.u32 rb, %1, %3;\n\t"
                        "cp.async.bulk.shared::cluster.shared::cta."
                        "mbarrier::complete_tx::bytes [ra], [%2], 512, [rb];\n\t}"
                        :: "r"(dst), "r"(mb), "r"(src), "r"(tc) : "memory");
                }
            }
        }
        // Warps 4-11 fall straight through to the next wait.
    }

    // Drain inbound copies before exit.
    mbar_wait_(mbar_u32, ph & 1u);
    asm volatile("barrier.cluster.arrive.aligned;" ::: "memory");
    asm volatile("barrier.cluster.wait.aligned;" ::: "memory");
}

// ---------------------------------------------------------------------------
extern "C" void kernel_launch(void* const* d_in, const int* in_sizes, int n_in,
                              void* d_out, int out_size)
{
    const float* x    = (const float*)d_in[0];
    const float* Wih0 = (const float*)d_in[1];
    const float* Whh0 = (const float*)d_in[2];
    const float* bih0 = (const float*)d_in[3];
    const float* bhh0 = (const float*)d_in[4];
    const float* Wih1 = (const float*)d_in[5];
    const float* Whh1 = (const float*)d_in[6];
    const float* bih1 = (const float*)d_in[7];
    const float* bhh1 = (const float*)d_in[8];
    const float* fcw  = (const float*)d_in[9];
    const float* fcb  = (const float*)d_in[10];
    float* out = (float*)d_out;

    float *gates, *h;
    cudaGetSymbolAddress((void**)&gates, g_gates);
    cudaGetSymbolAddress((void**)&h, g_h);

    const int M = B_ * T_;
    dim3 blk(256);

    gemm_nt<<<dim3(G3 / 64, M / 128), blk>>>(x, Wih0, bih0, gates, M, G3, I_);
    gru_scan<<<128, 384>>>(gates, Whh0, bhh0, h);

    gemm_nt<<<dim3(G3 / 64, M / 128), blk>>>(h, Wih1, bih1, gates, M, G3, H_);
    gru_scan<<<128, 384>>>(gates, Whh1, bhh1, h);

    gemm_nt<<<dim3(C_ / 64, M / 128), blk>>>(h, fcw, fcb, out, M, C_, H_);
}